// round 8
// baseline (speedup 1.0000x reference)
#include <cuda_runtime.h>

// CIF: continuous integrate-and-fire.
// hidden [B,T,H] f32, alphas [B,T] f32, target_lengths [B] i32 -> out [B,L,H] f32.
#define BB 32
#define TT 2000
#define HH 512
#define LL 256
#define THRESH 0.95f
#define CHUNK 25              // 2000 = 80 * 25
#define NCHUNK (TT / CHUNK)

// Scratch (no device allocation allowed -> __device__ globals).
__device__ int2  g_tok[BB * LL];      // (fire time t, __float_as_int(cur)) per token
__device__ int2  g_dummy_tok;         // sink for predicated-off token stores
__device__ float g_scale[BB];         // per-batch alpha rescale factor
__device__ int   g_ntok[BB];          // number of emitted tokens (<= LL)
__device__ float g_aT[TT * BB];       // transposed scaled alphas: [t*32 + b] (L2-resident)

// ---------------------------------------------------------------------------
// Fused kernel (256 threads — scan phase needs ~96 regs/thread, so a 1024-
// thread block would exceed the 64K RF; __launch_bounds__ pins legality).
// Phase 1: 8 warps, warp w sums batches {w, w+8, w+16, w+24} in double.
// Phase 2: smem-tiled transpose of scaled alphas into g_aT (coalesced).
// Phase 3: warp 0, lane b replays batch b's exact recurrence, branchless
//          (pointer-select token store -> no BSSY/BSYNC on the chain).
// ---------------------------------------------------------------------------
__global__ void __launch_bounds__(256, 1)
cif_scan_fused(const float* __restrict__ alphas,
               const int*   __restrict__ tlen)
{
    __shared__ float s_scale[BB];
    __shared__ float s_tile[128 * 33];     // [t_local][b], pad 33 -> conflict-free

    const int tid  = threadIdx.x;
    const int wid  = tid >> 5;             // 0..7
    const int lane = tid & 31;

    // ---- phase 1: per-batch double sum -> f32 scale
    #pragma unroll
    for (int r = 0; r < 4; r++) {
        const int b = wid + r * 8;
        const float* __restrict__ ab = alphas + (size_t)b * TT;
        double s = 0.0;
        for (int t = lane; t < TT; t += 32) s += (double)ab[t];
        #pragma unroll
        for (int o = 16; o > 0; o >>= 1)
            s += __shfl_down_sync(0xffffffffu, s, o);
        if (lane == 0) {
            const float sc = (float)tlen[b] / (float)s;
            s_scale[b] = sc;
            g_scale[b] = sc;
        }
    }
    __syncthreads();

    // ---- phase 2: transpose+scale into g_aT[t*32+b], tiles of [32 b][128 t]
    for (int t0 = 0; t0 < TT; t0 += 128) {
        for (int i = tid; i < 32 * 128; i += 256) {
            const int b = i >> 7, j = i & 127;      // consecutive j -> coalesced LDG
            const int t = t0 + j;
            if (t < TT) s_tile[j * 33 + b] = alphas[(size_t)b * TT + t];
        }
        __syncthreads();
        for (int i = tid; i < 32 * 128; i += 256) {
            const int tl = i >> 5, b = i & 31;      // consecutive b -> coalesced STG
            const int t = t0 + tl;
            if (t < TT) g_aT[t * BB + b] = s_tile[tl * 33 + b] * s_scale[b];
        }
        __syncthreads();
    }

    // ---- phase 3: warp 0 only; lane b scans batch b. Chain: FADD->FSETP->FSEL.
    if (wid == 0) {
        const int b = lane;
        int2* __restrict__ tok = g_tok + b * LL;
        const float* __restrict__ aT = g_aT;

        float integ = 0.0f;
        int   k     = 0;
        float bufA[CHUNK], bufB[CHUNK];

        #pragma unroll
        for (int i = 0; i < CHUNK; i++)
            bufA[i] = aT[i * BB + b];

        #define PROCESS(BUF, TBASE)                                           \
            _Pragma("unroll")                                                 \
            for (int i = 0; i < CHUNK; i++) {                                 \
                const float a    = (BUF)[i];                                  \
                const float cur  = 1.0f - integ;     /* dist_completion */    \
                const float snew = integ + a;        /* FADD  (chain)   */    \
                const bool  fire = (snew >= THRESH); /* FSETP (chain)   */    \
                const float sm1  = snew - 1.0f;      /* exact, Sterbenz */    \
                int2* p = (fire && (k < LL)) ? (tok + k) : &g_dummy_tok;      \
                *p = make_int2((TBASE) + i, __float_as_int(cur));             \
                k += fire;                                                    \
                integ = fire ? sm1 : snew;           /* FSEL  (chain)   */    \
            }

        for (int c = 0; c < NCHUNK; c += 2) {
            #pragma unroll
            for (int i = 0; i < CHUNK; i++)
                bufB[i] = aT[((c + 1) * CHUNK + i) * BB + b];
            PROCESS(bufA, c * CHUNK)
            #pragma unroll
            for (int i = 0; i < CHUNK; i++)
                bufA[i] = (c + 2 < NCHUNK) ? aT[((c + 2) * CHUNK + i) * BB + b] : 0.0f;
            PROCESS(bufB, (c + 1) * CHUNK)
        }
        #undef PROCESS

        g_ntok[b] = (k < LL) ? k : LL;
    }
}

// ---------------------------------------------------------------------------
// Gather: segmented weighted reduction of hidden -> out[b,k,:].
// Grid (L, B); 128 threads; thread owns one float4 (H=512). Boundary frames
// peeled; interior loop branch-free, unrolled x8.
// wfirst (remainds of previous fire) recomputed bit-exactly as a*scale - cur.
// ---------------------------------------------------------------------------
__global__ void cif_gather_kernel(const float* __restrict__ hidden,
                                  const float* __restrict__ alphas,
                                  float*       __restrict__ out)
{
    const int k   = blockIdx.x;
    const int b   = blockIdx.y;
    const int tid = threadIdx.x;

    float4 acc = make_float4(0.f, 0.f, 0.f, 0.f);

    const int ntok = g_ntok[b];
    if (k < ntok) {
        const int2  tk    = g_tok[b * LL + k];
        const int   t1    = tk.x;
        const float wlast = __int_as_float(tk.y);
        const float scale = g_scale[b];
        const float* __restrict__ ap = alphas + (size_t)b * TT;
        const float4* __restrict__ hbase =
            reinterpret_cast<const float4*>(hidden + (size_t)b * TT * HH) + tid;

        int tstart;
        if (k == 0) {
            tstart = 0;
        } else {
            const int2  tp      = g_tok[b * LL + k - 1];
            const int   t0      = tp.x;
            const float curprev = __int_as_float(tp.y);
            const float wfirst  = ap[t0] * scale - curprev;   // == remainds (bit-exact)
            const float4 h0 = hbase[(size_t)t0 * (HH / 4)];
            acc.x = wfirst * h0.x; acc.y = wfirst * h0.y;
            acc.z = wfirst * h0.z; acc.w = wfirst * h0.w;
            tstart = t0 + 1;
        }

        #pragma unroll 8
        for (int t = tstart; t < t1; t++) {
            const float  w = ap[t] * scale;
            const float4 h = hbase[(size_t)t * (HH / 4)];
            acc.x += w * h.x; acc.y += w * h.y;
            acc.z += w * h.z; acc.w += w * h.w;
        }

        {
            const float4 h = hbase[(size_t)t1 * (HH / 4)];
            acc.x += wlast * h.x; acc.y += wlast * h.y;
            acc.z += wlast * h.z; acc.w += wlast * h.w;
        }
    }

    reinterpret_cast<float4*>(out + (size_t)(b * LL + k) * HH)[tid] = acc;
}

// ---------------------------------------------------------------------------
extern "C" void kernel_launch(void* const* d_in, const int* in_sizes, int n_in,
                              void* d_out, int out_size)
{
    const float* hidden = (const float*)d_in[0];   // [B,T,H]
    const float* alphas = (const float*)d_in[1];   // [B,T]
    const int*   tlen   = (const int*)  d_in[2];   // [B]
    float*       out    = (float*)d_out;           // [B,L,H]

    cif_scan_fused<<<1, 256>>>(alphas, tlen);

    dim3 grid(LL, BB);
    cif_gather_kernel<<<grid, 128>>>(hidden, alphas, out);
}

// round 9
// speedup vs baseline: 1.4380x; 1.4380x over previous
#include <cuda_runtime.h>

// CIF: continuous integrate-and-fire.
// hidden [B,T,H] f32, alphas [B,T] f32, target_lengths [B] i32 -> out [B,L,H] f32.
#define BB 32
#define TT 2000
#define HH 512
#define LL 256
#define THRESH 0.95f
#define CHUNK 32
#define NCHUNK 63             // ceil(2000/32) = 63 (tail padded with a=0, never fires)
#define NF4 500               // float4s per alpha row

// Scratch (no device allocation allowed -> __device__ globals).
__device__ double g_part[BB * 8];     // per-(batch, 1/8-chunk) double partial sums
__device__ float  g_scale[BB];        // per-batch alpha rescale factor
__device__ int2   g_chk[NCHUNK * BB]; // per-chunk checkpoint: (bits(integ), k) at chunk start
__device__ int2   g_tok[BB * LL];     // (fire time t, bits(cur)) per token
__device__ int    g_ntok[BB];         // number of emitted tokens (<= LL)

// ---------------------------------------------------------------------------
// K1: parallel partial sums. Block (b,c) sums alphas[b, c*250 .. c*250+249]
// in double via smem tree. Fixed split -> deterministic.
// ---------------------------------------------------------------------------
__global__ void cif_partial_sum(const float* __restrict__ alphas)
{
    const int b = blockIdx.x >> 3;
    const int c = blockIdx.x & 7;
    __shared__ double red[256];
    const int i = threadIdx.x;

    double v = 0.0;
    if (i < 250) v = (double)alphas[(size_t)b * TT + c * 250 + i];
    red[i] = v;
    __syncthreads();
    #pragma unroll
    for (int o = 128; o > 0; o >>= 1) {
        if (i < o) red[i] += red[i + o];
        __syncthreads();
    }
    if (i == 0) g_part[b * 8 + c] = red[0];
}

// ---------------------------------------------------------------------------
// K2: 1-warp serial scan, lane b = batch b. ONLY the irreducible FP chain:
// FADD -> FSETP (pred-as-data) -> FSEL = 12 cyc/iter. No per-iter stores, no
// branches. Emits a (integ, k) checkpoint per 32-step chunk (63 STG.64 total).
// Per-lane float4 loads from its own alpha row, chunk-double-buffered
// (384-cyc chunk >> 260-cyc L2 latency).
// ---------------------------------------------------------------------------
__global__ void cif_scan(const float* __restrict__ alphas,
                         const int*   __restrict__ tlen)
{
    const int b = threadIdx.x;                 // 0..31

    // Finalize scale: fixed-order sum of 8 double partials.
    double s = 0.0;
    #pragma unroll
    for (int c = 0; c < 8; c++) s += g_part[b * 8 + c];
    const float scale = (float)tlen[b] / (float)s;
    g_scale[b] = scale;

    const float4* __restrict__ ap4 =
        reinterpret_cast<const float4*>(alphas + (size_t)b * TT);

    float bufA[CHUNK], bufB[CHUNK];

    #define LOADCHUNK(BUF, C)                                                  \
        _Pragma("unroll")                                                      \
        for (int j = 0; j < 8; j++) {                                          \
            const int idx = (C) * 8 + j;                                       \
            const float4 v = (idx < NF4) ? ap4[idx]                            \
                                         : make_float4(0.f, 0.f, 0.f, 0.f);    \
            (BUF)[j * 4 + 0] = v.x; (BUF)[j * 4 + 1] = v.y;                    \
            (BUF)[j * 4 + 2] = v.z; (BUF)[j * 4 + 3] = v.w;                    \
        }

    float integ = 0.0f;
    int   k     = 0;

    #define PROCESS(BUF, C)                                                    \
        g_chk[(C) * BB + b] = make_int2(__float_as_int(integ), k);             \
        _Pragma("unroll")                                                      \
        for (int i = 0; i < CHUNK; i++) {                                      \
            const float a    = (BUF)[i] * scale;   /* off-chain FMUL      */   \
            const float snew = integ + a;          /* FADD  (chain)       */   \
            const bool  fire = (snew >= THRESH);   /* FSETP (chain)       */   \
            const float sm1  = snew - 1.0f;        /* parallel FADD       */   \
            integ = fire ? sm1 : snew;             /* FSEL  (chain)       */   \
            k += fire;                             /* off-chain IADD      */   \
        }

    LOADCHUNK(bufA, 0)
    for (int c = 0; c < NCHUNK; c += 2) {
        LOADCHUNK(bufB, c + 1)
        PROCESS(bufA, c)
        LOADCHUNK(bufA, c + 2)
        if (c + 1 < NCHUNK) PROCESS(bufB, c + 1)
    }
    #undef PROCESS
    #undef LOADCHUNK

    g_ntok[b] = (k < LL) ? k : LL;
}

// ---------------------------------------------------------------------------
// K3: parallel expand. Thread (chunk c, batch b) replays its 32 steps from the
// checkpoint with IDENTICAL FP ops (same FMUL/FADD/compare) -> identical fire
// decisions -> writes g_tok records. 2016 independent threads.
// ---------------------------------------------------------------------------
__global__ void cif_expand(const float* __restrict__ alphas)
{
    const int c = blockIdx.x;                  // 0..62
    const int b = threadIdx.x;                 // 0..31

    const int2 rec = g_chk[c * BB + b];
    float integ = __int_as_float(rec.x);
    int   k     = rec.y;
    const float scale = g_scale[b];
    int2* __restrict__ tok = g_tok + b * LL;

    const float4* __restrict__ ap4 =
        reinterpret_cast<const float4*>(alphas + (size_t)b * TT);

    float av[CHUNK];
    #pragma unroll
    for (int j = 0; j < 8; j++) {
        const int idx = c * 8 + j;
        const float4 v = (idx < NF4) ? ap4[idx] : make_float4(0.f, 0.f, 0.f, 0.f);
        av[j * 4 + 0] = v.x; av[j * 4 + 1] = v.y;
        av[j * 4 + 2] = v.z; av[j * 4 + 3] = v.w;
    }

    const int tbase = c * CHUNK;
    #pragma unroll
    for (int i = 0; i < CHUNK; i++) {
        const float a    = av[i] * scale;
        const float cur  = 1.0f - integ;       // dist_completion (pre-add)
        const float snew = integ + a;
        const bool  fire = (snew >= THRESH);
        if (fire) {
            if (k < LL) tok[k] = make_int2(tbase + i, __float_as_int(cur));
            k++;
        }
        integ = fire ? (snew - 1.0f) : snew;
    }
}

// ---------------------------------------------------------------------------
// K4 (gather): segmented weighted reduction of hidden -> out[b,k,:].
// Grid (L, B); 128 threads; thread owns one float4 (H=512). Boundary frames
// peeled; interior loop branch-free, unrolled x8.
// wfirst (remainds of previous fire) recomputed bit-exactly as a*scale - cur.
// ---------------------------------------------------------------------------
__global__ void cif_gather_kernel(const float* __restrict__ hidden,
                                  const float* __restrict__ alphas,
                                  float*       __restrict__ out)
{
    const int k   = blockIdx.x;
    const int b   = blockIdx.y;
    const int tid = threadIdx.x;

    float4 acc = make_float4(0.f, 0.f, 0.f, 0.f);

    const int ntok = g_ntok[b];
    if (k < ntok) {
        const int2  tk    = g_tok[b * LL + k];
        const int   t1    = tk.x;
        const float wlast = __int_as_float(tk.y);
        const float scale = g_scale[b];
        const float* __restrict__ ap = alphas + (size_t)b * TT;
        const float4* __restrict__ hbase =
            reinterpret_cast<const float4*>(hidden + (size_t)b * TT * HH) + tid;

        int tstart;
        if (k == 0) {
            tstart = 0;
        } else {
            const int2  tp      = g_tok[b * LL + k - 1];
            const int   t0      = tp.x;
            const float curprev = __int_as_float(tp.y);
            const float wfirst  = ap[t0] * scale - curprev;   // == remainds (bit-exact)
            const float4 h0 = hbase[(size_t)t0 * (HH / 4)];
            acc.x = wfirst * h0.x; acc.y = wfirst * h0.y;
            acc.z = wfirst * h0.z; acc.w = wfirst * h0.w;
            tstart = t0 + 1;
        }

        #pragma unroll 8
        for (int t = tstart; t < t1; t++) {
            const float  w = ap[t] * scale;
            const float4 h = hbase[(size_t)t * (HH / 4)];
            acc.x += w * h.x; acc.y += w * h.y;
            acc.z += w * h.z; acc.w += w * h.w;
        }

        {
            const float4 h = hbase[(size_t)t1 * (HH / 4)];
            acc.x += wlast * h.x; acc.y += wlast * h.y;
            acc.z += wlast * h.z; acc.w += wlast * h.w;
        }
    }

    reinterpret_cast<float4*>(out + (size_t)(b * LL + k) * HH)[tid] = acc;
}

// ---------------------------------------------------------------------------
extern "C" void kernel_launch(void* const* d_in, const int* in_sizes, int n_in,
                              void* d_out, int out_size)
{
    const float* hidden = (const float*)d_in[0];   // [B,T,H]
    const float* alphas = (const float*)d_in[1];   // [B,T]
    const int*   tlen   = (const int*)  d_in[2];   // [B]
    float*       out    = (float*)d_out;           // [B,L,H]

    cif_partial_sum<<<BB * 8, 256>>>(alphas);
    cif_scan<<<1, 32>>>(alphas, tlen);
    cif_expand<<<NCHUNK, 32>>>(alphas);

    dim3 grid(LL, BB);
    cif_gather_kernel<<<grid, 128>>>(hidden, alphas, out);
}